// round 5
// baseline (speedup 1.0000x reference)
#include <cuda_runtime.h>
#include <cstdint>

#define Bn 16
#define Tn 512
#define En 2048
#define Hn 1024
#define Dn 128

// ---------------- scratch (device globals; no allocs allowed) ----------------
__device__ float              g_xw[(size_t)Bn * Tn * Hn]; // 32 MB: x@W_ih^T + biases
__device__ unsigned long long g_hx[2][Hn];                // tagged hidden: {tag:hi32, f32 bits:lo32}
__device__ float              g_hs[Bn * Hn];              // per-batch final hidden

// ---------------- init: must reset per launch (graph replays) ----------------
// Slot 1 tag 0 encodes initial h = 0 ("step -1 wrote tag 0").
// Slot 0 is only ever polled for odd tags, so tag 0 there is inert.
__global__ void init_kernel() {
    int tid = blockIdx.x * blockDim.x + threadIdx.x;
    if (tid < 2 * Hn) ((unsigned long long*)g_hx)[tid] = 0ull;
}

// ---------------- xW GEMM: C[8192,1024] = X[8192,2048] @ W_ih^T + (b_ih+b_hh) -
#define BM 128
#define BN 128
#define BK 16
#define SP 132   // padded smem row stride (floats)

__global__ __launch_bounds__(256, 2) void xw_gemm(
    const float* __restrict__ X, const float* __restrict__ Wih,
    const float* __restrict__ bih, const float* __restrict__ bhh,
    const int* __restrict__ lengths)
{
    const int m0 = blockIdx.x * BM;
    const int n0 = blockIdx.y * BN;
    const int b  = m0 / Tn;         // BM=128 divides Tn=512: tile stays inside one batch row
    const int t0 = m0 % Tn;
    if (t0 >= lengths[b]) return;   // fully-padded tile: its xw is never read

    __shared__ __align__(16) float As[BK * SP];
    __shared__ __align__(16) float Bs[BK * SP];

    const int tid = threadIdx.x;
    const int tx = tid & 15;
    const int ty = tid >> 4;

    float acc[8][8];
#pragma unroll
    for (int i = 0; i < 8; i++)
#pragma unroll
        for (int j = 0; j < 8; j++) acc[i][j] = 0.0f;

    for (int k0 = 0; k0 < En; k0 += BK) {
#pragma unroll
        for (int i = 0; i < 2; i++) {
            int idx = tid + i * 256;
            int m   = idx >> 2;
            int kq  = (idx & 3) << 2;
            float4 av = *(const float4*)&X  [(size_t)(m0 + m) * En + k0 + kq];
            float4 bv = *(const float4*)&Wih[(size_t)(n0 + m) * En + k0 + kq];
            As[(kq + 0) * SP + m] = av.x; As[(kq + 1) * SP + m] = av.y;
            As[(kq + 2) * SP + m] = av.z; As[(kq + 3) * SP + m] = av.w;
            Bs[(kq + 0) * SP + m] = bv.x; Bs[(kq + 1) * SP + m] = bv.y;
            Bs[(kq + 2) * SP + m] = bv.z; Bs[(kq + 3) * SP + m] = bv.w;
        }
        __syncthreads();
#pragma unroll
        for (int k = 0; k < BK; k++) {
            float4 a0 = *(const float4*)&As[k * SP + 4 * ty];
            float4 a1 = *(const float4*)&As[k * SP + 64 + 4 * ty];
            float4 b0 = *(const float4*)&Bs[k * SP + 4 * tx];
            float4 b1 = *(const float4*)&Bs[k * SP + 64 + 4 * tx];
            float ar[8] = {a0.x, a0.y, a0.z, a0.w, a1.x, a1.y, a1.z, a1.w};
            float br[8] = {b0.x, b0.y, b0.z, b0.w, b1.x, b1.y, b1.z, b1.w};
#pragma unroll
            for (int i = 0; i < 8; i++)
#pragma unroll
                for (int j = 0; j < 8; j++)
                    acc[i][j] = fmaf(ar[i], br[j], acc[i][j]);
        }
        __syncthreads();
    }

    float4 bi0 = *(const float4*)&bih[n0 + 4 * tx];
    float4 bh0 = *(const float4*)&bhh[n0 + 4 * tx];
    float4 bi1 = *(const float4*)&bih[n0 + 64 + 4 * tx];
    float4 bh1 = *(const float4*)&bhh[n0 + 64 + 4 * tx];
    float4 c0 = make_float4(bi0.x + bh0.x, bi0.y + bh0.y, bi0.z + bh0.z, bi0.w + bh0.w);
    float4 c1 = make_float4(bi1.x + bh1.x, bi1.y + bh1.y, bi1.z + bh1.z, bi1.w + bh1.w);
#pragma unroll
    for (int i = 0; i < 8; i++) {
        int m = m0 + ((i < 4) ? (4 * ty + i) : (64 + 4 * ty + i - 4));
        float4 o0 = make_float4(acc[i][0] + c0.x, acc[i][1] + c0.y,
                                acc[i][2] + c0.z, acc[i][3] + c0.w);
        float4 o1 = make_float4(acc[i][4] + c1.x, acc[i][5] + c1.y,
                                acc[i][6] + c1.z, acc[i][7] + c1.w);
        *(float4*)&g_xw[(size_t)m * Hn + n0 + 4 * tx]      = o0;
        *(float4*)&g_xw[(size_t)m * Hn + n0 + 64 + 4 * tx] = o1;
    }
}

// ---------------- sequential recurrence: tagged dataflow, no global barrier ---
// 128 CTAs (1/SM, co-resident), 128 threads. CTA c owns rows [8c,8c+8) of W_hh
// in REGISTERS (warp w -> rows 2w,2w+1; lane l -> k = l+32j).
// Step s: poll slot[(s+1)&1] for tag s (thread tid owns CTA tid's 8 rows;
// tag+value share one relaxed u64 -> no tearing, no fences).
// POLL STRATEGY (round-5 fix): spin ONLY on a sentinel word (word 0 of the 8)
// -- 8x less spin traffic than re-reading all 8 -- then fetch the remaining 7
// once and retry just the stale ones via a pending mask. Keeps L2 unloaded so
// the writer->reader hop stays ~250cyc instead of congestion-inflated 600+.
// hsh is DOUBLE-BUFFERED (step&1): with the one __syncthreads per step, warp
// skew is bounded to one iteration, so writer(s+1)/reader(s) never collide.
// Inter-CTA slot reuse safe: the g_hx store sits AFTER the barrier, so a
// tag-(s+1) write witnesses its whole CTA's step-s poll; all tags s+1 present
// => every thread everywhere finished reading that slot for step s.
#define NBLK 128
#define RPC  8

__global__ __launch_bounds__(128, 1) void rnn_kernel(
    const float* __restrict__ Whh, const int* __restrict__ lengths)
{
    __shared__ __align__(16) float hsh[2][Hn];   // 8 KB staged h, double-buffered

    const int tid  = threadIdx.x;
    const int cta  = blockIdx.x;
    const int w    = tid >> 5;
    const int lane = tid & 31;
    const int gr0  = cta * RPC + 2 * w;   // this warp's two output rows
    const int gr1  = gr0 + 1;

    // one-time: W_hh rows into registers (coalesced: lane-stride 4B per j)
    float wr0[32], wr1[32];
#pragma unroll
    for (int j = 0; j < 32; j++) {
        wr0[j] = __ldg(&Whh[(size_t)gr0 * Hn + lane + 32 * j]);
        wr1[j] = __ldg(&Whh[(size_t)gr1 * Hn + lane + 32 * j]);
    }

    unsigned int step = 0;
    for (int b = 0; b < Bn; b++) {
        const int L = __ldg(&lengths[b]);
        const float* xwb = g_xw + (size_t)b * Tn * Hn;
        for (int t = 0; t < L; t++) {
            // prefetch xw for this warp's rows (independent of h; overlaps poll)
            float xwv = 0.0f;
            if (lane < 2) xwv = __ldcg(&xwb[(size_t)t * Hn + gr0 + lane]);

            const unsigned long long* src = g_hx[(step + 1) & 1u] + tid * 8;
            const unsigned int tag = step;

            // ---- phase 1: cheap sentinel spin (8B/thread/round) ----
            unsigned long long e0;
            do {
                asm volatile("ld.relaxed.gpu.global.u64 %0, [%1];"
                             : "=l"(e0) : "l"(src) : "memory");
            } while ((unsigned int)(e0 >> 32) != tag);

            // ---- phase 2: fetch remaining 7, retry only stale (pending mask)
            unsigned long long e[8];
            e[0] = e0;
            unsigned int pend = 0xFEu;
            do {
#pragma unroll
                for (int i = 1; i < 8; i++) {
                    if (pend & (1u << i)) {
                        asm volatile("ld.relaxed.gpu.global.u64 %0, [%1];"
                                     : "=l"(e[i]) : "l"(src + i) : "memory");
                        if ((unsigned int)(e[i] >> 32) == tag) pend &= ~(1u << i);
                    }
                }
            } while (pend);

            // stage values into this step's hsh buffer (2x STS.128)
            float* hcur = hsh[step & 1u];
            float4* dst = (float4*)&hcur[tid * 8];
            dst[0] = make_float4(__uint_as_float((unsigned int)e[0]),
                                 __uint_as_float((unsigned int)e[1]),
                                 __uint_as_float((unsigned int)e[2]),
                                 __uint_as_float((unsigned int)e[3]));
            dst[1] = make_float4(__uint_as_float((unsigned int)e[4]),
                                 __uint_as_float((unsigned int)e[5]),
                                 __uint_as_float((unsigned int)e[6]),
                                 __uint_as_float((unsigned int)e[7]));
            __syncthreads();

            // ---- matvec from registers: 64 FMA + 32 conflict-free LDS.32 ----
            float a0 = 0.f, a1 = 0.f, b0 = 0.f, b1 = 0.f;
#pragma unroll
            for (int j = 0; j < 32; j += 2) {
                float h0 = hcur[lane + 32 * j];
                float h1 = hcur[lane + 32 * (j + 1)];
                a0 = fmaf(h0, wr0[j],     a0);
                b0 = fmaf(h0, wr1[j],     b0);
                a1 = fmaf(h1, wr0[j + 1], a1);
                b1 = fmaf(h1, wr1[j + 1], b1);
            }
            float sA = a0 + a1;
            float sB = b0 + b1;
#pragma unroll
            for (int off = 16; off > 0; off >>= 1) {
                sA += __shfl_xor_sync(0xffffffffu, sA, off);
                sB += __shfl_xor_sync(0xffffffffu, sB, off);
            }

            // lanes 0 and 1 each finish one row: tanh + tagged relaxed u64 store
            if (lane < 2) {
                float hn = tanhf(xwv + (lane ? sB : sA));
                unsigned long long pk =
                    ((unsigned long long)(step + 1u) << 32) |
                    (unsigned long long)__float_as_uint(hn);
                asm volatile("st.relaxed.gpu.global.u64 [%0], %1;"
                             :: "l"(&g_hx[step & 1u][gr0 + lane]), "l"(pk)
                             : "memory");
                if (t == L - 1) __stcg(&g_hs[b * Hn + gr0 + lane], hn);
            }
            step++;
        }
    }
}

// ---------------- head: out[16,128] = hs @ W_l1^T + b_l1 ----------------------
__global__ void head_kernel(const float* __restrict__ Wl1,
                            const float* __restrict__ bl1,
                            float* __restrict__ out)
{
    const int b = blockIdx.x;
    const int d = threadIdx.x;   // 128
    __shared__ float hsh[Hn];
    for (int i = d; i < Hn; i += Dn) hsh[i] = g_hs[b * Hn + i];
    __syncthreads();

    float acc = bl1[d];
    const float* wr = Wl1 + (size_t)d * Hn;
#pragma unroll 4
    for (int k = 0; k < Hn; k += 4) {
        float4 wv = *(const float4*)&wr[k];
        acc = fmaf(wv.x, hsh[k + 0], acc);
        acc = fmaf(wv.y, hsh[k + 1], acc);
        acc = fmaf(wv.z, hsh[k + 2], acc);
        acc = fmaf(wv.w, hsh[k + 3], acc);
    }
    out[b * Dn + d] = acc;
}

// ---------------- launch ------------------------------------------------------
extern "C" void kernel_launch(void* const* d_in, const int* in_sizes, int n_in,
                              void* d_out, int out_size)
{
    const float* x       = (const float*)d_in[0];
    const int*   lengths = (const int*)  d_in[1];
    const float* W_ih    = (const float*)d_in[2];
    const float* W_hh    = (const float*)d_in[3];
    const float* b_ih    = (const float*)d_in[4];
    const float* b_hh    = (const float*)d_in[5];
    const float* W_l1    = (const float*)d_in[6];
    const float* b_l1    = (const float*)d_in[7];
    float* out = (float*)d_out;

    init_kernel<<<8, 256>>>();

    dim3 grid(Bn * Tn / BM, Hn / BN);
    xw_gemm<<<grid, 256>>>(x, W_ih, b_ih, b_hh, lengths);

    rnn_kernel<<<NBLK, 128>>>(W_hh, lengths);

    head_kernel<<<Bn, Dn>>>(W_l1, b_l1, out);
}

// round 6
// speedup vs baseline: 2.1094x; 2.1094x over previous
#include <cuda_runtime.h>
#include <cstdint>

#define Bn 16
#define Tn 512
#define En 2048
#define Hn 1024
#define Dn 128

// ---------------- scratch (device globals; no allocs allowed) ----------------
__device__ float        g_xw[(size_t)Bn * Tn * Hn];  // 32 MB: x@W_ih^T + biases
__device__ float        g_hv[2][Hn];                 // double-buffered hidden state
__device__ unsigned int g_flag[128 * 32];            // per-CTA progress flag, one 128B line each
__device__ float        g_hs[Bn * Hn];               // per-batch final hidden

// ---------------- init: must reset per launch (graph replays) ----------------
__global__ void init_kernel() {
    int tid = blockIdx.x * blockDim.x + threadIdx.x;
    if (tid < 2 * Hn) ((float*)g_hv)[tid] = 0.0f;        // h init = 0 (both slots)
    if (tid < 128 * 32) g_flag[tid] = 0u;                // 0 completed iters
}

// ---------------- xW GEMM: C[8192,1024] = X[8192,2048] @ W_ih^T + (b_ih+b_hh) -
#define BM 128
#define BN 128
#define BK 16
#define SP 132   // padded smem row stride (floats)

__global__ __launch_bounds__(256, 2) void xw_gemm(
    const float* __restrict__ X, const float* __restrict__ Wih,
    const float* __restrict__ bih, const float* __restrict__ bhh,
    const int* __restrict__ lengths)
{
    const int m0 = blockIdx.x * BM;
    const int n0 = blockIdx.y * BN;
    const int b  = m0 / Tn;         // BM=128 divides Tn=512: tile stays inside one batch row
    const int t0 = m0 % Tn;
    if (t0 >= lengths[b]) return;   // fully-padded tile: its xw is never read

    __shared__ __align__(16) float As[BK * SP];
    __shared__ __align__(16) float Bs[BK * SP];

    const int tid = threadIdx.x;
    const int tx = tid & 15;
    const int ty = tid >> 4;

    float acc[8][8];
#pragma unroll
    for (int i = 0; i < 8; i++)
#pragma unroll
        for (int j = 0; j < 8; j++) acc[i][j] = 0.0f;

    for (int k0 = 0; k0 < En; k0 += BK) {
#pragma unroll
        for (int i = 0; i < 2; i++) {
            int idx = tid + i * 256;
            int m   = idx >> 2;
            int kq  = (idx & 3) << 2;
            float4 av = *(const float4*)&X  [(size_t)(m0 + m) * En + k0 + kq];
            float4 bv = *(const float4*)&Wih[(size_t)(n0 + m) * En + k0 + kq];
            As[(kq + 0) * SP + m] = av.x; As[(kq + 1) * SP + m] = av.y;
            As[(kq + 2) * SP + m] = av.z; As[(kq + 3) * SP + m] = av.w;
            Bs[(kq + 0) * SP + m] = bv.x; Bs[(kq + 1) * SP + m] = bv.y;
            Bs[(kq + 2) * SP + m] = bv.z; Bs[(kq + 3) * SP + m] = bv.w;
        }
        __syncthreads();
#pragma unroll
        for (int k = 0; k < BK; k++) {
            float4 a0 = *(const float4*)&As[k * SP + 4 * ty];
            float4 a1 = *(const float4*)&As[k * SP + 64 + 4 * ty];
            float4 b0 = *(const float4*)&Bs[k * SP + 4 * tx];
            float4 b1 = *(const float4*)&Bs[k * SP + 64 + 4 * tx];
            float ar[8] = {a0.x, a0.y, a0.z, a0.w, a1.x, a1.y, a1.z, a1.w};
            float br[8] = {b0.x, b0.y, b0.z, b0.w, b1.x, b1.y, b1.z, b1.w};
#pragma unroll
            for (int i = 0; i < 8; i++)
#pragma unroll
                for (int j = 0; j < 8; j++)
                    acc[i][j] = fmaf(ar[i], br[j], acc[i][j]);
        }
        __syncthreads();
    }

    float4 bi0 = *(const float4*)&bih[n0 + 4 * tx];
    float4 bh0 = *(const float4*)&bhh[n0 + 4 * tx];
    float4 bi1 = *(const float4*)&bih[n0 + 64 + 4 * tx];
    float4 bh1 = *(const float4*)&bhh[n0 + 64 + 4 * tx];
    float4 c0 = make_float4(bi0.x + bh0.x, bi0.y + bh0.y, bi0.z + bh0.z, bi0.w + bh0.w);
    float4 c1 = make_float4(bi1.x + bh1.x, bi1.y + bh1.y, bi1.z + bh1.z, bi1.w + bh1.w);
#pragma unroll
    for (int i = 0; i < 8; i++) {
        int m = m0 + ((i < 4) ? (4 * ty + i) : (64 + 4 * ty + i - 4));
        float4 o0 = make_float4(acc[i][0] + c0.x, acc[i][1] + c0.y,
                                acc[i][2] + c0.z, acc[i][3] + c0.w);
        float4 o1 = make_float4(acc[i][4] + c1.x, acc[i][5] + c1.y,
                                acc[i][6] + c1.z, acc[i][7] + c1.w);
        *(float4*)&g_xw[(size_t)m * Hn + n0 + 4 * tx]      = o0;
        *(float4*)&g_xw[(size_t)m * Hn + n0 + 64 + 4 * tx] = o1;
    }
}

// ---------------- sequential recurrence: per-CTA-flag dataflow ---------------
// 128 CTAs (all co-resident: 128 <= 148 SMs), 128 threads. CTA c owns rows
// [8c,8c+8) of W_hh in REGISTERS (warp w -> rows 2w,2w+1; lane l -> k=l+32j).
//
// Protocol (iter s, 0-based global step over all (b,t)):
//   read  slot[(s+1)&1]  (h produced at iter s-1; init zeros for s=0)
//   write slot[s&1]
//   flag[c] = s+1 (st.release.gpu, after a __syncthreads covering all 8 rows)
// Consumer thread tid polls ONLY flag[tid] (4B acquire, dedicated 128B line ->
// no contention) until >= s, then ONE-SHOT ldcg of that CTA's 64B h-slice:
// flag implies the whole slice is ready -- no per-row tags, no retry loops
// (the R4/R5 failure modes). Slices stage into double-buffered smem as
// producers land, hiding h-load latency behind the straggler's flag.
//
// Safety: flag[c] >= s (acquire) => CTA c finished iter s-1, and its reads of
// slot[s&1] precede its flag via program order + syncthreads + release. So a
// writer touching slot[s&1] at iter s cannot race any iter-(s-1) reader.
// Intra-CTA: hsh double-buffered; 2 barriers/iter bound warp skew to one iter.
#define NBLK 128
#define RPC  8

__global__ __launch_bounds__(128, 1) void rnn_kernel(
    const float* __restrict__ Whh, const int* __restrict__ lengths)
{
    __shared__ __align__(16) float hsh[2][Hn];   // 8 KB staged h, double-buffered

    const int tid  = threadIdx.x;
    const int cta  = blockIdx.x;
    const int w    = tid >> 5;
    const int lane = tid & 31;
    const int gr0  = cta * RPC + 2 * w;   // this warp's two output rows
    const int gr1  = gr0 + 1;

    // one-time: W_hh rows into registers (coalesced: lane-stride 4B per j)
    float wr0[32], wr1[32];
#pragma unroll
    for (int j = 0; j < 32; j++) {
        wr0[j] = __ldg(&Whh[(size_t)gr0 * Hn + lane + 32 * j]);
        wr1[j] = __ldg(&Whh[(size_t)gr1 * Hn + lane + 32 * j]);
    }

    const unsigned int* myflag = &g_flag[tid * 32];

    unsigned int step = 0;
    for (int b = 0; b < Bn; b++) {
        const int L = __ldg(&lengths[b]);
        const float* xwb = g_xw + (size_t)b * Tn * Hn;
        for (int t = 0; t < L; t++) {
            // prefetch xw for this warp's rows (independent of h; overlaps poll)
            float xwv = 0.0f;
            if (lane < 2) xwv = __ldcg(&xwb[(size_t)t * Hn + gr0 + lane]);

            // ---- poll producer-CTA tid's flag (acquire), light backoff ----
            unsigned int v;
            for (;;) {
                asm volatile("ld.acquire.gpu.global.u32 %0, [%1];"
                             : "=r"(v) : "l"(myflag) : "memory");
                if (v >= step) break;
                __nanosleep(64);
            }

            // ---- one-shot fetch of that CTA's 8-row slice (64B, coalesced) ----
            const float4* hp = (const float4*)&g_hv[(step + 1) & 1u][tid * 8];
            float4 h0, h1;
            asm volatile("ld.global.cg.v4.f32 {%0,%1,%2,%3}, [%4];"
                         : "=f"(h0.x), "=f"(h0.y), "=f"(h0.z), "=f"(h0.w)
                         : "l"(hp) : "memory");
            asm volatile("ld.global.cg.v4.f32 {%0,%1,%2,%3}, [%4];"
                         : "=f"(h1.x), "=f"(h1.y), "=f"(h1.z), "=f"(h1.w)
                         : "l"(hp + 1) : "memory");

            float* hcur = hsh[step & 1u];
            float4* dst = (float4*)&hcur[tid * 8];
            dst[0] = h0;
            dst[1] = h1;
            __syncthreads();

            // ---- matvec from registers: 64 FMA + 32 conflict-free LDS.32 ----
            float a0 = 0.f, a1 = 0.f, b0 = 0.f, b1 = 0.f;
#pragma unroll
            for (int j = 0; j < 32; j += 2) {
                float hA = hcur[lane + 32 * j];
                float hB = hcur[lane + 32 * (j + 1)];
                a0 = fmaf(hA, wr0[j],     a0);
                b0 = fmaf(hA, wr1[j],     b0);
                a1 = fmaf(hB, wr0[j + 1], a1);
                b1 = fmaf(hB, wr1[j + 1], b1);
            }
            float sA = a0 + a1;
            float sB = b0 + b1;
#pragma unroll
            for (int off = 16; off > 0; off >>= 1) {
                sA += __shfl_xor_sync(0xffffffffu, sA, off);
                sB += __shfl_xor_sync(0xffffffffu, sB, off);
            }

            // lanes 0,1 each finish one row: tanh + plain store (released by flag)
            if (lane < 2) {
                float hn = tanhf(xwv + (lane ? sB : sA));
                __stcg(&g_hv[step & 1u][gr0 + lane], hn);
                if (t == L - 1) __stcg(&g_hs[b * Hn + gr0 + lane], hn);
            }
            __syncthreads();   // all warps' h stores precede the flag release

            if (tid == 0) {
                unsigned int nf = step + 1u;
                asm volatile("st.release.gpu.global.u32 [%0], %1;"
                             :: "l"(&g_flag[cta * 32]), "r"(nf) : "memory");
            }
            step++;
        }
    }
}

// ---------------- head: out[16,128] = hs @ W_l1^T + b_l1 ----------------------
__global__ void head_kernel(const float* __restrict__ Wl1,
                            const float* __restrict__ bl1,
                            float* __restrict__ out)
{
    const int b = blockIdx.x;
    const int d = threadIdx.x;   // 128
    __shared__ float hsh[Hn];
    for (int i = d; i < Hn; i += Dn) hsh[i] = g_hs[b * Hn + i];
    __syncthreads();

    float acc = bl1[d];
    const float* wr = Wl1 + (size_t)d * Hn;
#pragma unroll 4
    for (int k = 0; k < Hn; k += 4) {
        float4 wv = *(const float4*)&wr[k];
        acc = fmaf(wv.x, hsh[k + 0], acc);
        acc = fmaf(wv.y, hsh[k + 1], acc);
        acc = fmaf(wv.z, hsh[k + 2], acc);
        acc = fmaf(wv.w, hsh[k + 3], acc);
    }
    out[b * Dn + d] = acc;
}

// ---------------- launch ------------------------------------------------------
extern "C" void kernel_launch(void* const* d_in, const int* in_sizes, int n_in,
                              void* d_out, int out_size)
{
    const float* x       = (const float*)d_in[0];
    const int*   lengths = (const int*)  d_in[1];
    const float* W_ih    = (const float*)d_in[2];
    const float* W_hh    = (const float*)d_in[3];
    const float* b_ih    = (const float*)d_in[4];
    const float* b_hh    = (const float*)d_in[5];
    const float* W_l1    = (const float*)d_in[6];
    const float* b_l1    = (const float*)d_in[7];
    float* out = (float*)d_out;

    init_kernel<<<16, 256>>>();

    dim3 grid(Bn * Tn / BM, Hn / BN);
    xw_gemm<<<grid, 256>>>(x, W_ih, b_ih, b_hh, lengths);

    rnn_kernel<<<NBLK, 128>>>(W_hh, lengths);

    head_kernel<<<Bn, Dn>>>(W_l1, b_l1, out);
}